// round 4
// baseline (speedup 1.0000x reference)
#include <cuda_runtime.h>
#include <cuda_bf16.h>
#include <cstdint>

// Problem constants
#define M_DIM 4096
#define K_DIM 4096
#define N_DIM 11008

// GEMM tiling (int8 path)
#define MBLK 128
#define NBLK 256
#define KC   128                      // K elems per chunk (128 int8 = 128B row, SW128)
#define NKC  (K_DIM / KC)             // 32 chunks
#define STAGES 4
#define A_TILE_BYTES (MBLK * KC)      // 16384
#define B_TILE_BYTES (NBLK * KC)      // 32768
#define STAGE_BYTES  (A_TILE_BYTES + B_TILE_BYTES)   // 49152
#define SMEM_HDR 1024
#define SMEM_TOTAL (SMEM_HDR + STAGES * STAGE_BYTES) // 197632

#define NWARPS_C 16      // compute warps (4 m x 4 n)
#define NTHREADS 544     // 16 compute + 1 producer warp

// ------------------------------------------------------------------
// Device scratch: pre-swizzled, tile-contiguous int8 operands
//   g_qx_t : [mblk=32][kc=32][128x128 s8 tile, SW128]  (16 MB)
//   g_w_t  : [nblk=43][kc=32][256x128 s8 tile, SW128]  (44 MB)
//   g_rowsum[m] = sum_k qi[m,k]  (for zero-point correction)
// ------------------------------------------------------------------
__device__ uint4 g_qx_t[(size_t)M_DIM * K_DIM / 16];
__device__ uint4 g_w_t[(size_t)N_DIM * K_DIM / 16];
__device__ int   g_rowsum[M_DIM];

// ------------------------------------------------------------------
// PTX helpers (base sm_90-level only; NO tcgen05 / no 'a' features)
// ------------------------------------------------------------------
__device__ __forceinline__ uint32_t smem_u32(const void* p) {
    uint32_t a;
    asm("{ .reg .u64 t; cvta.to.shared.u64 t, %1; cvt.u32.u64 %0, t; }" : "=r"(a) : "l"(p));
    return a;
}

__device__ __forceinline__ bool elect1() {
    uint32_t p;
    asm volatile("{ .reg .pred p; elect.sync _|p, 0xFFFFFFFF; selp.b32 %0, 1, 0, p; }" : "=r"(p));
    return p != 0;
}

__device__ __forceinline__ void mbar_init(uint32_t a, uint32_t n) {
    asm volatile("mbarrier.init.shared.b64 [%0], %1;" :: "r"(a), "r"(n) : "memory");
}
__device__ __forceinline__ void mbar_expect(uint32_t a, uint32_t bytes) {
    asm volatile("mbarrier.arrive.expect_tx.shared.b64 _, [%0], %1;" :: "r"(a), "r"(bytes) : "memory");
}
__device__ __forceinline__ void mbar_arrive(uint32_t a) {
    asm volatile("mbarrier.arrive.shared.b64 _, [%0];" :: "r"(a) : "memory");
}
__device__ __forceinline__ void mbar_wait(uint32_t a, uint32_t ph) {
    asm volatile(
        "{\n\t.reg .pred P;\n\t"
        "WAIT_LOOP_%=:\n\t"
        "mbarrier.try_wait.parity.acquire.cta.shared::cta.b64 P, [%0], %1, 0x989680;\n\t"
        "@P bra.uni WAIT_DONE_%=;\n\t"
        "bra.uni WAIT_LOOP_%=;\n\t"
        "WAIT_DONE_%=:\n\t}"
        :: "r"(a), "r"(ph) : "memory");
}

__device__ __forceinline__ void bulk_g2s(uint32_t dst, const void* src, uint32_t bytes, uint32_t mbar) {
    asm volatile(
        "cp.async.bulk.shared::cluster.global.mbarrier::complete_tx::bytes [%0], [%1], %2, [%3];"
        :: "r"(dst), "l"(src), "r"(bytes), "r"(mbar) : "memory");
}

__device__ __forceinline__ void ldsm4(uint32_t* r, uint32_t addr) {
    asm volatile("ldmatrix.sync.aligned.m8n8.x4.shared.b16 {%0,%1,%2,%3}, [%4];"
        : "=r"(r[0]), "=r"(r[1]), "=r"(r[2]), "=r"(r[3]) : "r"(addr));
}

__device__ __forceinline__ void imma16832(int* c, const uint32_t* a, const uint32_t* b) {
    asm volatile(
        "mma.sync.aligned.m16n8k32.row.col.s32.s8.s8.s32 "
        "{%0,%1,%2,%3}, {%4,%5,%6,%7}, {%8,%9}, {%0,%1,%2,%3};"
        : "+r"(c[0]), "+r"(c[1]), "+r"(c[2]), "+r"(c[3])
        : "r"(a[0]), "r"(a[1]), "r"(a[2]), "r"(a[3]), "r"(b[0]), "r"(b[1]));
}

// SW128 (Swizzle<3,4,3>) on byte offsets within a 128B-row tile
__device__ __forceinline__ uint32_t sw128(uint32_t o) { return o ^ ((o >> 3) & 0x70); }

// ------------------------------------------------------------------
// Kernel 0: zero rowsum accumulator
// ------------------------------------------------------------------
__global__ void k_zero() {
    int i = blockIdx.x * blockDim.x + threadIdx.x;
    if (i < M_DIM) g_rowsum[i] = 0;
}

// ------------------------------------------------------------------
// Kernel 1: quantize x -> int8 qi, pre-swizzled tiled layout + rowsums
// one thread handles 16 consecutive k (one 16B swizzle unit)
// ------------------------------------------------------------------
__global__ void k_quant(const float* __restrict__ x, const float* __restrict__ clampv) {
    uint32_t idx = blockIdx.x * blockDim.x + threadIdx.x;
    if (idx >= (uint32_t)(M_DIM * (K_DIM / 16))) return;
    uint32_t m = idx >> 8;          // row
    uint32_t g = idx & 255;         // group of 16 k
    float cv = clampv[0];
    float inv = 127.0f / cv;

    const float4* xp = reinterpret_cast<const float4*>(x + (size_t)m * K_DIM + g * 16);
    float v[16];
#pragma unroll
    for (int i = 0; i < 4; i++) {
        float4 f = xp[i];
        v[4 * i] = f.x; v[4 * i + 1] = f.y; v[4 * i + 2] = f.z; v[4 * i + 3] = f.w;
    }

    int rsum = 0;
    uint32_t pk[4];
#pragma unroll
    for (int i = 0; i < 4; i++) {
        uint32_t w = 0;
#pragma unroll
        for (int j = 0; j < 4; j++) {
            int q = (int)rintf(fminf(fmaxf(v[4 * i + j], -cv), cv) * inv);
            rsum += q;
            w |= (uint32_t)(q & 0xFF) << (8 * j);
        }
        pk[i] = w;
    }

    // warp-level rowsum reduction (whole warp is in the same row: 256 groups/row)
#pragma unroll
    for (int off = 16; off > 0; off >>= 1)
        rsum += __shfl_xor_sync(0xFFFFFFFFu, rsum, off);
    if ((threadIdx.x & 31) == 0) atomicAdd(&g_rowsum[m], rsum);

    uint32_t r = m & 127, kc = g >> 3, cb = (g & 7) * 16;
    uint32_t off = sw128(r * 128 + cb);
    size_t tile = (size_t)(m >> 7) * NKC + kc;
    *reinterpret_cast<uint4*>(reinterpret_cast<char*>(g_qx_t) + tile * A_TILE_BYTES + off) =
        make_uint4(pk[0], pk[1], pk[2], pk[3]);
}

// ------------------------------------------------------------------
// Kernel 2: unpack int4 nibbles -> s8 (zero-point NOT applied; handled
// in epilogue via rowsum), pre-swizzled tiled layout
// ------------------------------------------------------------------
__global__ void k_unpack(const int* __restrict__ qw) {
    uint32_t idx = blockIdx.x * blockDim.x + threadIdx.x;
    if (idx >= (uint32_t)(N_DIM * (K_DIM / 16))) return;
    uint32_t o = idx >> 8;          // output row
    uint32_t g = idx & 255;         // group of 16 k (= 8 packed int32)

    const int4* qp = reinterpret_cast<const int4*>(qw + (size_t)o * (K_DIM / 2) + g * 8);
    int4 w0 = qp[0], w1 = qp[1];
    int wsrc[8] = {w0.x, w0.y, w0.z, w0.w, w1.x, w1.y, w1.z, w1.w};

    uint32_t pk[4];
#pragma unroll
    for (int i = 0; i < 4; i++) {
        int a = wsrc[2 * i], b = wsrc[2 * i + 1];
        uint32_t b0 = (a >> 4) & 15;   // even k
        uint32_t b1 = a & 15;          // odd k
        uint32_t b2 = (b >> 4) & 15;
        uint32_t b3 = b & 15;
        pk[i] = b0 | (b1 << 8) | (b2 << 16) | (b3 << 24);
    }

    uint32_t r = o & 255, kc = g >> 3, cb = (g & 7) * 16;
    uint32_t off = sw128(r * 128 + cb);
    size_t tile = (size_t)(o >> 8) * NKC + kc;
    *reinterpret_cast<uint4*>(reinterpret_cast<char*>(g_w_t) + tile * B_TILE_BYTES + off) =
        make_uint4(pk[0], pk[1], pk[2], pk[3]);
}

// ------------------------------------------------------------------
// Kernel 3: int8 IMMA GEMM, 128x256 CTA tile
//   16 compute warps (4m x 4n, warp tile 32x64) + 1 producer warp
//   4-stage cp.async.bulk + mbarrier pipeline on pre-swizzled tiles
// ------------------------------------------------------------------
__global__ void __launch_bounds__(NTHREADS, 1) k_gemm(
    const float* __restrict__ scales, const float* __restrict__ bias,
    const int* __restrict__ qz, const float* __restrict__ clampv,
    float* __restrict__ out)
{
    extern __shared__ char smem[];
    const uint32_t sb = smem_u32(smem);
    const int tid = threadIdx.x;
    const int wid = tid >> 5;
    const int lid = tid & 31;
    const uint32_t mblk = blockIdx.x;
    const uint32_t nblk = blockIdx.y;

    // header: full[s] @ sb + s*8 ; empty[s] @ sb + 64 + s*8
    const uint32_t tbase = sb + SMEM_HDR;

    if (tid == 0) {
#pragma unroll
        for (int s = 0; s < STAGES; s++) {
            mbar_init(sb + s * 8, 1);             // full: completed by expect_tx bytes
            mbar_init(sb + 64 + s * 8, NWARPS_C); // empty: 16 warp arrivals
        }
        asm volatile("fence.proxy.async.shared::cta;" ::: "memory");
    }
    __syncthreads();

    if (wid == NWARPS_C) {
        // ---------- producer warp ----------
        if (elect1()) {
            const char* Ab = reinterpret_cast<const char*>(g_qx_t) + (size_t)mblk * NKC * A_TILE_BYTES;
            const char* Bb = reinterpret_cast<const char*>(g_w_t)  + (size_t)nblk * NKC * B_TILE_BYTES;
#pragma unroll
            for (int c = 0; c < STAGES; c++) {   // prologue: fill all stages
                uint32_t dst = tbase + c * STAGE_BYTES;
                mbar_expect(sb + c * 8, STAGE_BYTES);
                bulk_g2s(dst,                Ab + (size_t)c * A_TILE_BYTES, A_TILE_BYTES, sb + c * 8);
                bulk_g2s(dst + A_TILE_BYTES, Bb + (size_t)c * B_TILE_BYTES, B_TILE_BYTES, sb + c * 8);
            }
            for (int cn = STAGES; cn < NKC; cn++) {
                int s = cn % STAGES;
                uint32_t ep = (((cn / STAGES) & 1)) ^ 1;
                mbar_wait(sb + 64 + s * 8, ep);
                uint32_t dst = tbase + s * STAGE_BYTES;
                mbar_expect(sb + s * 8, STAGE_BYTES);
                bulk_g2s(dst,                Ab + (size_t)cn * A_TILE_BYTES, A_TILE_BYTES, sb + s * 8);
                bulk_g2s(dst + A_TILE_BYTES, Bb + (size_t)cn * B_TILE_BYTES, B_TILE_BYTES, sb + s * 8);
            }
        }
        return;
    }

    // ---------- compute warps ----------
    const int wm = wid >> 2;    // 0..3 : M sub-tile of 32 rows
    const int wn = wid & 3;     // 0..3 : N sub-tile of 64 cols

    int acc[2][8][4];
#pragma unroll
    for (int i = 0; i < 2; i++)
#pragma unroll
        for (int j = 0; j < 8; j++)
#pragma unroll
            for (int t = 0; t < 4; t++) acc[i][j][t] = 0;

    // per-thread intra-tile offsets (16B k-granules, 128B rows)
    // A: m0 rows0-7 k0-15 | m1 rows8-15 k0-15 | m2 rows0-7 k16-31 | m3 rows8-15 k16-31
    const uint32_t aRow  = (uint32_t)(wm * 32 + (lid & 15));      // + mt*16
    const uint32_t aColB = (uint32_t)((lid >> 4) * 16);           // + ks*32
    // B: m0 n0-7 k0-15 | m1 n0-7 k16-31 | m2 n8-15 k0-15 | m3 n8-15 k16-31
    const uint32_t bRow  = (uint32_t)(wn * 64 + (lid & 7) + ((lid >> 4) << 3));  // + np*16
    const uint32_t bColB = (uint32_t)(((lid >> 3) & 1) * 16);     // + ks*32

    for (int c = 0; c < NKC; c++) {
        int s = c % STAGES;
        mbar_wait(sb + s * 8, (uint32_t)((c / STAGES) & 1));
        const uint32_t aT = tbase + s * STAGE_BYTES;
        const uint32_t bT = aT + A_TILE_BYTES;

#pragma unroll
        for (int ks = 0; ks < 4; ks++) {          // 4 x K=32 steps cover KC=128
            const uint32_t k0 = ks * 32;
            uint32_t a[2][4];
#pragma unroll
            for (int mt = 0; mt < 2; mt++)
                ldsm4(a[mt], aT + sw128((aRow + mt * 16) * 128 + k0 + aColB));
            uint32_t b[4][4];
#pragma unroll
            for (int np = 0; np < 4; np++)
                ldsm4(b[np], bT + sw128((bRow + np * 16) * 128 + k0 + bColB));
#pragma unroll
            for (int mt = 0; mt < 2; mt++)
#pragma unroll
                for (int nt = 0; nt < 8; nt++)
                    imma16832(acc[mt][nt], a[mt], &b[nt >> 1][(nt & 1) * 2]);
        }
        __syncwarp();
        if (lid == 0) mbar_arrive(sb + 64 + s * 8);
    }

    // ---------- epilogue: asc*s[n]*(acc - z[n]*rowsum[m]) + bias[n] ----------
    const float asc = clampv[0] * (1.0f / 127.0f);
    const int mbase = mblk * MBLK + wm * 32;
    const int nbase = nblk * NBLK + wn * 64;

    const int rA = mbase + (lid >> 2);
    const int rs[2][2] = {{g_rowsum[rA], g_rowsum[rA + 8]},
                          {g_rowsum[rA + 16], g_rowsum[rA + 24]}};

#pragma unroll
    for (int nt = 0; nt < 8; nt++) {
        const int c0 = nbase + nt * 8 + (lid & 3) * 2;
        const float s0 = scales[c0] * asc, s1 = scales[c0 + 1] * asc;
        const float b0 = bias[c0], b1 = bias[c0 + 1];
        const int z0 = qz[c0], z1 = qz[c0 + 1];
#pragma unroll
        for (int mt = 0; mt < 2; mt++) {
            const int r0 = mbase + mt * 16 + (lid >> 2);
            float2 v0, v1;
            v0.x = (float)(acc[mt][nt][0] - z0 * rs[mt][0]) * s0 + b0;
            v0.y = (float)(acc[mt][nt][1] - z1 * rs[mt][0]) * s1 + b1;
            v1.x = (float)(acc[mt][nt][2] - z0 * rs[mt][1]) * s0 + b0;
            v1.y = (float)(acc[mt][nt][3] - z1 * rs[mt][1]) * s1 + b1;
            *reinterpret_cast<float2*>(out + (size_t)r0 * N_DIM + c0) = v0;
            *reinterpret_cast<float2*>(out + (size_t)(r0 + 8) * N_DIM + c0) = v1;
        }
    }
}

// ------------------------------------------------------------------
// Launch
// inputs: x f32 [4096,4096], qweight i32 [11008,2048], qzeros i32 [11008],
//         scales f32 [11008], bias f32 [11008], clampv f32 [1]
// output: f32 [4096,11008]
// ------------------------------------------------------------------
extern "C" void kernel_launch(void* const* d_in, const int* in_sizes, int n_in,
                              void* d_out, int out_size) {
    const float* x      = (const float*)d_in[0];
    const int*   qw     = (const int*)d_in[1];
    const int*   qz     = (const int*)d_in[2];
    const float* scales = (const float*)d_in[3];
    const float* bias   = (const float*)d_in[4];
    const float* clampv = (const float*)d_in[5];
    float* out = (float*)d_out;

    k_zero<<<(M_DIM + 255) / 256, 256>>>();
    k_quant<<<(M_DIM * (K_DIM / 16)) / 256, 256>>>(x, clampv);
    k_unpack<<<(N_DIM * (K_DIM / 16) + 255) / 256, 256>>>(qw);

    cudaFuncSetAttribute(k_gemm, cudaFuncAttributeMaxDynamicSharedMemorySize, SMEM_TOTAL);

    dim3 grid(M_DIM / MBLK, N_DIM / NBLK);   // (32, 43): M fastest -> A stays L2-resident
    k_gemm<<<grid, NTHREADS, SMEM_TOTAL>>>(scales, bias, qz, clampv, out);
}

// round 6
// speedup vs baseline: 3.2597x; 3.2597x over previous
#include <cuda_runtime.h>
#include <cuda_bf16.h>
#include <cstdint>

// Problem constants
#define M_DIM 4096
#define K_DIM 4096
#define N_DIM 11008

// GEMM tiling (bf16 HMMA path, occupancy-2)
#define MBLK 128
#define NBLK 128
#define KC   64                       // K elems per chunk (64 bf16 = 128B row, SW128)
#define NKC  (K_DIM / KC)             // 64 chunks
#define STAGES 3
#define A_TILE_BYTES (MBLK * KC * 2)  // 16384
#define B_TILE_BYTES (NBLK * KC * 2)  // 16384
#define STAGE_BYTES  (A_TILE_BYTES + B_TILE_BYTES)   // 32768
#define SMEM_HDR 1024
#define SMEM_TOTAL (SMEM_HDR + STAGES * STAGE_BYTES) // 99328  (x2 CTAs = 198656 < 228K)

#define NWARPS_C 8       // compute warps (4 m x 2 n), warp tile 32x64
#define NTHREADS 288     // 8 compute + 1 producer warp

// ------------------------------------------------------------------
// Device scratch: pre-swizzled, tile-contiguous bf16 operands
//   g_qx_t : [mblk=32][kc=64][128x64 bf16 tile, SW128]  (32 MB)
//   g_w_t  : [nblk=86][kc=64][128x64 bf16 tile, SW128]  (88 MB)
// ------------------------------------------------------------------
__device__ uint4 g_qx_t[(size_t)M_DIM * K_DIM * 2 / 16];
__device__ uint4 g_w_t[(size_t)N_DIM * K_DIM * 2 / 16];

// ------------------------------------------------------------------
// PTX helpers (base sm_90-level only; NO tcgen05 / no 'a' features)
// ------------------------------------------------------------------
__device__ __forceinline__ uint32_t smem_u32(const void* p) {
    uint32_t a;
    asm("{ .reg .u64 t; cvta.to.shared.u64 t, %1; cvt.u32.u64 %0, t; }" : "=r"(a) : "l"(p));
    return a;
}

__device__ __forceinline__ bool elect1() {
    uint32_t p;
    asm volatile("{ .reg .pred p; elect.sync _|p, 0xFFFFFFFF; selp.b32 %0, 1, 0, p; }" : "=r"(p));
    return p != 0;
}

__device__ __forceinline__ void mbar_init(uint32_t a, uint32_t n) {
    asm volatile("mbarrier.init.shared.b64 [%0], %1;" :: "r"(a), "r"(n) : "memory");
}
__device__ __forceinline__ void mbar_expect(uint32_t a, uint32_t bytes) {
    asm volatile("mbarrier.arrive.expect_tx.shared.b64 _, [%0], %1;" :: "r"(a), "r"(bytes) : "memory");
}
__device__ __forceinline__ void mbar_arrive(uint32_t a) {
    asm volatile("mbarrier.arrive.shared.b64 _, [%0];" :: "r"(a) : "memory");
}
__device__ __forceinline__ void mbar_wait(uint32_t a, uint32_t ph) {
    asm volatile(
        "{\n\t.reg .pred P;\n\t"
        "WAIT_LOOP_%=:\n\t"
        "mbarrier.try_wait.parity.acquire.cta.shared::cta.b64 P, [%0], %1, 0x989680;\n\t"
        "@P bra.uni WAIT_DONE_%=;\n\t"
        "bra.uni WAIT_LOOP_%=;\n\t"
        "WAIT_DONE_%=:\n\t}"
        :: "r"(a), "r"(ph) : "memory");
}

__device__ __forceinline__ void bulk_g2s(uint32_t dst, const void* src, uint32_t bytes, uint32_t mbar) {
    asm volatile(
        "cp.async.bulk.shared::cluster.global.mbarrier::complete_tx::bytes [%0], [%1], %2, [%3];"
        :: "r"(dst), "l"(src), "r"(bytes), "r"(mbar) : "memory");
}

__device__ __forceinline__ void ldsm4(uint32_t* r, uint32_t addr) {
    asm volatile("ldmatrix.sync.aligned.m8n8.x4.shared.b16 {%0,%1,%2,%3}, [%4];"
        : "=r"(r[0]), "=r"(r[1]), "=r"(r[2]), "=r"(r[3]) : "r"(addr));
}

__device__ __forceinline__ void mma16816(float* c, const uint32_t* a, const uint32_t* b) {
    asm volatile(
        "mma.sync.aligned.m16n8k16.row.col.f32.bf16.bf16.f32 "
        "{%0,%1,%2,%3}, {%4,%5,%6,%7}, {%8,%9}, {%0,%1,%2,%3};"
        : "+f"(c[0]), "+f"(c[1]), "+f"(c[2]), "+f"(c[3])
        : "r"(a[0]), "r"(a[1]), "r"(a[2]), "r"(a[3]), "r"(b[0]), "r"(b[1]));
}

// SW128 (Swizzle<3,4,3>) on byte offsets within a 128B-row tile
__device__ __forceinline__ uint32_t sw128(uint32_t o) { return o ^ ((o >> 3) & 0x70); }

// ------------------------------------------------------------------
// Kernel 1: quantize x -> bf16 integer qi, pre-swizzled tiled layout
// one thread handles 8 consecutive k (one 16B swizzle unit)
// ------------------------------------------------------------------
__global__ void k_quant(const float* __restrict__ x, const float* __restrict__ clampv) {
    uint32_t idx = blockIdx.x * blockDim.x + threadIdx.x;
    if (idx >= (uint32_t)(M_DIM * (K_DIM / 8))) return;
    uint32_t m = idx >> 9;          // row
    uint32_t g = idx & 511;         // group of 8 k
    float cv = clampv[0];
    float inv = 127.0f / cv;

    const float4* xp = reinterpret_cast<const float4*>(x + (size_t)m * K_DIM + g * 8);
    float4 a = xp[0], b = xp[1];
    float q[8] = {a.x, a.y, a.z, a.w, b.x, b.y, b.z, b.w};

    uint32_t pk[4];
#pragma unroll
    for (int i = 0; i < 4; i++) {
        float v0 = rintf(fminf(fmaxf(q[2 * i + 0], -cv), cv) * inv);
        float v1 = rintf(fminf(fmaxf(q[2 * i + 1], -cv), cv) * inv);
        __nv_bfloat162 h = __floats2bfloat162_rn(v0, v1);
        pk[i] = *reinterpret_cast<uint32_t*>(&h);
    }

    uint32_t mb = m >> 7, r = m & 127, kc = g >> 3, c = (g & 7) * 8;
    uint32_t off = sw128(r * 128 + c * 2);
    size_t tile = (size_t)mb * NKC + kc;
    *reinterpret_cast<uint4*>(reinterpret_cast<char*>(g_qx_t) + tile * A_TILE_BYTES + off) =
        make_uint4(pk[0], pk[1], pk[2], pk[3]);
}

// ------------------------------------------------------------------
// Kernel 2: unpack int4 - zero -> bf16, pre-swizzled 128-row N tiles
// ------------------------------------------------------------------
__global__ void k_unpack(const int* __restrict__ qw, const int* __restrict__ qz) {
    uint32_t idx = blockIdx.x * blockDim.x + threadIdx.x;
    if (idx >= (uint32_t)(N_DIM * (K_DIM / 8))) return;
    uint32_t o = idx >> 9;          // output row
    uint32_t g = idx & 511;         // group of 8 k (= 4 packed int32)
    int z = qz[o];

    int4 qq = *reinterpret_cast<const int4*>(qw + (size_t)o * (K_DIM / 2) + g * 4);
    int qv[4] = {qq.x, qq.y, qq.z, qq.w};

    uint32_t pk[4];
#pragma unroll
    for (int i = 0; i < 4; i++) {
        int hi = (qv[i] >> 4) & 15;   // even k
        int lo = qv[i] & 15;          // odd k
        __nv_bfloat162 h = __floats2bfloat162_rn((float)(hi - z), (float)(lo - z));
        pk[i] = *reinterpret_cast<uint32_t*>(&h);
    }

    uint32_t nb = o >> 7, r = o & 127, kc = g >> 3, c = (g & 7) * 8;
    uint32_t off = sw128(r * 128 + c * 2);
    size_t tile = (size_t)nb * NKC + kc;
    *reinterpret_cast<uint4*>(reinterpret_cast<char*>(g_w_t) + tile * B_TILE_BYTES + off) =
        make_uint4(pk[0], pk[1], pk[2], pk[3]);
}

// ------------------------------------------------------------------
// Kernel 3: warp-mma bf16 GEMM, 128x128 CTA tile, 2 CTAs/SM
//   8 compute warps (4m x 2n, warp tile 32x64) + 1 producer warp
//   3-stage cp.async.bulk + mbarrier pipeline on pre-swizzled tiles
// ------------------------------------------------------------------
__global__ void __launch_bounds__(NTHREADS, 2) k_gemm(
    const float* __restrict__ scales, const float* __restrict__ bias,
    const float* __restrict__ clampv, float* __restrict__ out)
{
    extern __shared__ char smem[];
    const uint32_t sb = smem_u32(smem);
    const int tid = threadIdx.x;
    const int wid = tid >> 5;
    const int lid = tid & 31;
    const uint32_t mblk = blockIdx.x;
    const uint32_t nblk = blockIdx.y;

    // header: full[s] @ sb + s*8 ; empty[s] @ sb + 64 + s*8
    const uint32_t tbase = sb + SMEM_HDR;

    if (tid == 0) {
#pragma unroll
        for (int s = 0; s < STAGES; s++) {
            mbar_init(sb + s * 8, 1);             // full: completed by expect_tx bytes
            mbar_init(sb + 64 + s * 8, NWARPS_C); // empty: 8 warp arrivals
        }
        asm volatile("fence.proxy.async.shared::cta;" ::: "memory");
    }
    __syncthreads();

    if (wid == NWARPS_C) {
        // ---------- producer warp ----------
        if (elect1()) {
            const char* Ab = reinterpret_cast<const char*>(g_qx_t) + (size_t)mblk * NKC * A_TILE_BYTES;
            const char* Bb = reinterpret_cast<const char*>(g_w_t)  + (size_t)nblk * NKC * B_TILE_BYTES;
#pragma unroll
            for (int c = 0; c < STAGES; c++) {   // prologue: fill all stages
                uint32_t dst = tbase + c * STAGE_BYTES;
                mbar_expect(sb + c * 8, STAGE_BYTES);
                bulk_g2s(dst,                Ab + (size_t)c * A_TILE_BYTES, A_TILE_BYTES, sb + c * 8);
                bulk_g2s(dst + A_TILE_BYTES, Bb + (size_t)c * B_TILE_BYTES, B_TILE_BYTES, sb + c * 8);
            }
            for (int cn = STAGES; cn < NKC; cn++) {
                int s = cn % STAGES;
                uint32_t ep = (((cn / STAGES) & 1)) ^ 1;   // wait (cn/STAGES - 1)-th release
                mbar_wait(sb + 64 + s * 8, ep);
                uint32_t dst = tbase + s * STAGE_BYTES;
                mbar_expect(sb + s * 8, STAGE_BYTES);
                bulk_g2s(dst,                Ab + (size_t)cn * A_TILE_BYTES, A_TILE_BYTES, sb + s * 8);
                bulk_g2s(dst + A_TILE_BYTES, Bb + (size_t)cn * B_TILE_BYTES, B_TILE_BYTES, sb + s * 8);
            }
        }
        return;
    }

    // ---------- compute warps ----------
    const int wm = wid >> 1;    // 0..3 : M sub-tile of 32 rows
    const int wn = wid & 1;     // 0..1 : N sub-tile of 64 cols

    float acc[2][8][4];
#pragma unroll
    for (int i = 0; i < 2; i++)
#pragma unroll
        for (int j = 0; j < 8; j++)
#pragma unroll
            for (int t = 0; t < 4; t++) acc[i][j][t] = 0.0f;

    // per-thread intra-tile offsets (verified fragment layouts)
    const uint32_t aRow  = (uint32_t)(wm * 32 + (lid & 15));      // + mt*16
    const uint32_t aColB = (uint32_t)((lid >> 4) << 3);           // + k0
    const uint32_t bRow  = (uint32_t)(wn * 64 + (lid & 7) + ((lid >> 4) << 3));  // + np*16
    const uint32_t bColB = (uint32_t)(((lid >> 3) & 1) << 3);     // + k0

    for (int c = 0; c < NKC; c++) {
        int s = c % STAGES;
        mbar_wait(sb + s * 8, (uint32_t)((c / STAGES) & 1));
        const uint32_t aT = tbase + s * STAGE_BYTES;
        const uint32_t bT = aT + A_TILE_BYTES;

#pragma unroll
        for (int ks = 0; ks < 4; ks++) {
            const uint32_t k0 = ks * 16;
            uint32_t a[2][4];
#pragma unroll
            for (int mt = 0; mt < 2; mt++)
                ldsm4(a[mt], aT + sw128((aRow + mt * 16) * 128 + (k0 + aColB) * 2));
            uint32_t b[4][4];
#pragma unroll
            for (int np = 0; np < 4; np++)
                ldsm4(b[np], bT + sw128((bRow + np * 16) * 128 + (k0 + bColB) * 2));
            // release stage as soon as this warp's last smem read for it is done
            if (ks == 3 && lid == 0) mbar_arrive(sb + 64 + s * 8);
#pragma unroll
            for (int mt = 0; mt < 2; mt++)
#pragma unroll
                for (int nt = 0; nt < 8; nt++)
                    mma16816(acc[mt][nt], a[mt], &b[nt >> 1][(nt & 1) * 2]);
        }
    }

    // ---------- epilogue: scale * acc + bias ----------
    const float asc = clampv[0] * (1.0f / 127.0f);
    const int mbase = mblk * MBLK + wm * 32;
    const int nbase = nblk * NBLK + wn * 64;

#pragma unroll
    for (int nt = 0; nt < 8; nt++) {
        const int c0 = nbase + nt * 8 + (lid & 3) * 2;
        const float s0 = scales[c0] * asc, s1 = scales[c0 + 1] * asc;
        const float b0 = bias[c0], b1 = bias[c0 + 1];
#pragma unroll
        for (int mt = 0; mt < 2; mt++) {
            const int r0 = mbase + mt * 16 + (lid >> 2);
            float2 v0, v1;
            v0.x = acc[mt][nt][0] * s0 + b0;
            v0.y = acc[mt][nt][1] * s1 + b1;
            v1.x = acc[mt][nt][2] * s0 + b0;
            v1.y = acc[mt][nt][3] * s1 + b1;
            *reinterpret_cast<float2*>(out + (size_t)r0 * N_DIM + c0) = v0;
            *reinterpret_cast<float2*>(out + (size_t)(r0 + 8) * N_DIM + c0) = v1;
        }
    }
}

// ------------------------------------------------------------------
// Launch
// inputs: x f32 [4096,4096], qweight i32 [11008,2048], qzeros i32 [11008],
//         scales f32 [11008], bias f32 [11008], clampv f32 [1]
// output: f32 [4096,11008]
// ------------------------------------------------------------------
extern "C" void kernel_launch(void* const* d_in, const int* in_sizes, int n_in,
                              void* d_out, int out_size) {
    const float* x      = (const float*)d_in[0];
    const int*   qw     = (const int*)d_in[1];
    const int*   qz     = (const int*)d_in[2];
    const float* scales = (const float*)d_in[3];
    const float* bias   = (const float*)d_in[4];
    const float* clampv = (const float*)d_in[5];
    float* out = (float*)d_out;

    k_quant<<<(M_DIM * (K_DIM / 8)) / 256, 256>>>(x, clampv);
    k_unpack<<<(N_DIM * (K_DIM / 8) + 255) / 256, 256>>>(qw, qz);

    cudaFuncSetAttribute(k_gemm, cudaFuncAttributeMaxDynamicSharedMemorySize, SMEM_TOTAL);

    dim3 grid(M_DIM / MBLK, N_DIM / NBLK);   // (32, 86): M fastest -> A stays L2-resident
    k_gemm<<<grid, NTHREADS, SMEM_TOTAL>>>(scales, bias, clampv, out);
}